// round 7
// baseline (speedup 1.0000x reference)
#include <cuda_runtime.h>
#include <cstdint>

// Neural CDE, B=128, T=1024, D=32, H=64, W=128.
// Cluster-resident: 16 clusters x 8 CTAs (grid=128, 512 thr). Each cluster
// owns 8 batches; vW2 (2112x128 fp32) sliced 264 rows/CTA, RESIDENT in SMEM
// (no per-step weight streaming -> beats the chip-LTS streaming ceiling).
// Per step: 3 tiny activation all-gathers via st.shared::cluster pushes
// (mapa-precomputed addresses) ordered by barrier.cluster (release/acquire).

namespace {

constexpr int Tn = 1024;
constexpr int Dn = 32;
constexpr int Hn = 64;
constexpr int Wn = 128;
constexpr int Cn = Dn + 1;     // 33
constexpr int On = Hn * Cn;    // 2112
constexpr int CG = 8;          // CTAs per cluster
constexpr int NBc = 8;         // batches per cluster
constexpr int ROWS = On / CG;  // 264 vW2 rows per CTA  (= 8 h-values x 33)
constexpr int RSL = Wn / CG;   // 16 layer-1/2 rows per CTA
constexpr int NT = 512;

struct __align__(16) Smem {
  float w2[ROWS * 132];    // 139392 B, rows padded 128->132 (conflict-free)
  float w1[RSL * 132];     // vW1 slice
  float w0s[RSL * 68];     // vW0 slice, cols 1..64 (+4 zero pad)
  float w0t[RSL];          // vW0 col 0 (t coefficient)
  float b0s[RSL], b1s[RSL];
  float b2s[ROWS];
  float yh[NBc * 68];      // gathered yhat  [b*68 + h]   (pads zero)
  float z1g[NBc * 132];    // gathered z1    [b*132 + k]
  float z2g[NBc * 132];    // gathered z2
  float v[NBc * 264];      // local v slice  [b*264 + hl*33 + c]
  float dx[NBc * 36];
  float tcur;
  float pad_[3];
};

__device__ __forceinline__ uint32_t smem_u32(const void* p) {
  return (uint32_t)__cvta_generic_to_shared(const_cast<void*>(p));
}
__device__ __forceinline__ uint32_t ctarank() {
  uint32_t r; asm("mov.u32 %0, %%cluster_ctarank;" : "=r"(r)); return r;
}
__device__ __forceinline__ uint32_t mapa_rank(uint32_t laddr, uint32_t rank) {
  uint32_t r;
  asm("mapa.shared::cluster.u32 %0, %1, %2;" : "=r"(r) : "r"(laddr), "r"(rank));
  return r;
}
__device__ __forceinline__ void st_cluster(uint32_t addr, float v) {
  asm volatile("st.shared::cluster.f32 [%0], %1;" :: "r"(addr), "f"(v) : "memory");
}
__device__ __forceinline__ void cluster_sync() {
  asm volatile("barrier.cluster.arrive.aligned;" ::: "memory");
  asm volatile("barrier.cluster.wait.aligned;" ::: "memory");
}

__device__ __forceinline__ float lipswish(float x) {
  float e = __expf(-x);
  return __fdividef(0.909f * x, 1.0f + e);
}
__device__ __forceinline__ float fast_tanh(float x) {
  float p = __expf(2.0f * x);
  return 1.0f - __fdividef(2.0f, p + 1.0f);
}
__device__ __forceinline__ float dot4(float4 a, float4 b, float acc) {
  acc = fmaf(a.x, b.x, acc);
  acc = fmaf(a.y, b.y, acc);
  acc = fmaf(a.z, b.z, acc);
  acc = fmaf(a.w, b.w, acc);
  return acc;
}

// One vf evaluation. Caller has already pushed yhat to all ranks' sm.yh and
// set sm.tcur. Phases separated by cluster barriers (release/acquire orders
// the st.shared::cluster pushes). Ends with __syncthreads (v visible).
__device__ __forceinline__ void vf_eval(Smem& sm, int tid,
                                        const uint32_t* z1r,
                                        const uint32_t* z2r) {
  cluster_sync();  // #1 : yh complete cluster-wide

  // ---- layer 1 slice: rows rl(16/CTA) x 8 batches; 128 threads ----
  if (tid < 128) {
    const int rl = tid >> 3, b = tid & 7;
    float a = sm.b0s[rl] + sm.w0t[rl] * sm.tcur;
    const float4* wr = reinterpret_cast<const float4*>(&sm.w0s[rl * 68]);
    const float4* yr = reinterpret_cast<const float4*>(&sm.yh[b * 68]);
#pragma unroll
    for (int q = 0; q < 17; ++q) a = dot4(wr[q], yr[q], a);
    const float z = lipswish(a);
#pragma unroll
    for (int r = 0; r < 8; ++r) st_cluster(z1r[r], z);
  }
  cluster_sync();  // #2 : z1g complete

  // ---- layer 2 slice ----
  if (tid < 128) {
    const int rl = tid >> 3, b = tid & 7;
    float a = sm.b1s[rl];
    const float4* wr = reinterpret_cast<const float4*>(&sm.w1[rl * 132]);
    const float4* zr = reinterpret_cast<const float4*>(&sm.z1g[b * 132]);
#pragma unroll
    for (int q = 0; q < 32; ++q) a = dot4(wr[q], zr[q], a);
    const float z = lipswish(a);
#pragma unroll
    for (int r = 0; r < 8; ++r) st_cluster(z2r[r], z);
  }
  cluster_sync();  // #3 : z2g complete

  // ---- layer 3: local 264-row resident slice x 8 batches ----
#pragma unroll
  for (int i = 0; i < 4; ++i) {
    const int idx = tid + 512 * i;          // 0..2047
    const int lr = idx >> 3, b = idx & 7;
    const float4* wr = reinterpret_cast<const float4*>(&sm.w2[lr * 132]);
    const float4* zr = reinterpret_cast<const float4*>(&sm.z2g[b * 132]);
    float a0 = 0.f, a1 = 0.f;
#pragma unroll
    for (int q = 0; q < 16; ++q) {
      a0 = dot4(wr[q], zr[q], a0);
      a1 = dot4(wr[q + 16], zr[q + 16], a1);
    }
    sm.v[b * 264 + lr] = fast_tanh(a0 + a1 + sm.b2s[lr]);
  }
  if (tid < 64) {                            // tail rows 256..263
    const int lr = 256 + (tid >> 3), b = tid & 7;
    const float4* wr = reinterpret_cast<const float4*>(&sm.w2[lr * 132]);
    const float4* zr = reinterpret_cast<const float4*>(&sm.z2g[b * 132]);
    float a0 = 0.f, a1 = 0.f;
#pragma unroll
    for (int q = 0; q < 16; ++q) {
      a0 = dot4(wr[q], zr[q], a0);
      a1 = dot4(wr[q + 16], zr[q + 16], a1);
    }
    sm.v[b * 264 + lr] = fast_tanh(a0 + a1 + sm.b2s[lr]);
  }
  __syncthreads();  // v visible CTA-locally
}

__global__ void __launch_bounds__(NT, 1) __cluster_dims__(CG, 1, 1)
ncde_kernel(const float* __restrict__ ts, const float* __restrict__ ys,
            const float* __restrict__ iW0, const float* __restrict__ ib0,
            const float* __restrict__ iW1, const float* __restrict__ ib1,
            const float* __restrict__ iW2, const float* __restrict__ ib2,
            const float* __restrict__ vW0, const float* __restrict__ vb0,
            const float* __restrict__ vW1, const float* __restrict__ vb1,
            const float* __restrict__ vW2, const float* __restrict__ vb2,
            const float* __restrict__ rW, const float* __restrict__ rb,
            float* __restrict__ out) {
  extern __shared__ char smem_raw[];
  Smem& sm = *reinterpret_cast<Smem*>(smem_raw);
  const int tid = threadIdx.x;
  const uint32_t rank = ctarank();
  const int cluster_b0 = (int)blockIdx.x - (int)rank;  // first batch of cluster

  // ---- load resident weight slices ----
  for (int i = tid; i < ROWS * Wn; i += NT) {
    const int lr = i >> 7, k = i & 127;
    sm.w2[lr * 132 + k] = vW2[(size_t)(ROWS * rank + lr) * Wn + k];
  }
  for (int i = tid; i < RSL * Wn; i += NT) {
    const int rl = i >> 7, k = i & 127;
    sm.w1[rl * 132 + k] = vW1[(RSL * rank + rl) * Wn + k];
  }
  for (int i = tid; i < RSL * 64; i += NT) {
    const int rl = i >> 6, j = i & 63;
    sm.w0s[rl * 68 + j] = vW0[(RSL * rank + rl) * (Hn + 1) + 1 + j];
  }
  if (tid < RSL) {
    sm.w0t[tid] = vW0[(RSL * rank + tid) * (Hn + 1)];
    sm.b0s[tid] = vb0[RSL * rank + tid];
    sm.b1s[tid] = vb1[RSL * rank + tid];
  }
  for (int i = tid; i < ROWS; i += NT) sm.b2s[i] = vb2[ROWS * rank + i];
  if (tid < 64) sm.w0s[(tid >> 2) * 68 + 64 + (tid & 3)] = 0.0f;  // w0s pads
  if (tid < 32) sm.yh[(tid >> 2) * 68 + 64 + (tid & 3)] = 0.0f;   // yh pads

  // ---- precompute remote push addresses (mapa once) ----
  const int b_t = tid & 7;     // batch lane
  const int q_t = tid >> 3;    // sub-row lane
  uint32_t yh_rem[8], z1_rem[8], z2_rem[8];
  {
    const uint32_t a_yh = smem_u32(&sm.yh[b_t * 68 + 8 * (int)rank + (q_t & 7)]);
    const uint32_t a_z1 = smem_u32(&sm.z1g[b_t * 132 + RSL * (int)rank + (q_t & 15)]);
    const uint32_t a_z2 = smem_u32(&sm.z2g[b_t * 132 + RSL * (int)rank + (q_t & 15)]);
#pragma unroll
    for (int r = 0; r < 8; ++r) {
      yh_rem[r] = mapa_rank(a_yh, (uint32_t)r);
      z1_rem[r] = mapa_rank(a_z1, (uint32_t)r);
      z2_rem[r] = mapa_rank(a_z2, (uint32_t)r);
    }
  }

  // ---- x prefetch (tid < 264) ----
  const int b_p = tid / Cn;
  const int c_p = tid - b_p * Cn;
  const int gb_p = cluster_b0 + b_p;
  float xp = 0.f, xn = 0.f;
  if (tid < NBc * Cn) {
    xp = (c_p == 0) ? ts[0] : ys[((size_t)gb_p * Tn) * Dn + (c_p - 1)];
    xn = (c_p == 0) ? ts[1] : ys[((size_t)gb_p * Tn + 1) * Dn + (c_p - 1)];
    sm.dx[b_p * 36 + c_p] = xp;  // stage x0 for initial MLP
  }
  if (tid == 0) sm.tcur = ts[0];
  __syncthreads();

  // ---- initial MLP (redundant per CTA; z1g/z2g as scratch) ----
  for (int u = tid; u < Wn * NBc; u += NT) {
    const int r = u >> 3, b = u & 7;
    float a = ib0[r];
    for (int j = 0; j < Cn; ++j) a = fmaf(iW0[r * Cn + j], sm.dx[b * 36 + j], a);
    sm.z1g[b * 132 + r] = fmaxf(a, 0.f);
  }
  __syncthreads();
  for (int u = tid; u < Wn * NBc; u += NT) {
    const int r = u >> 3, b = u & 7;
    float a = ib1[r];
    const float4* wr = reinterpret_cast<const float4*>(iW1 + (size_t)r * Wn);
    const float4* zr = reinterpret_cast<const float4*>(&sm.z1g[b * 132]);
    for (int f = 0; f < 32; ++f) a = dot4(wr[f], zr[f], a);
    sm.z2g[b * 132 + r] = fmaxf(a, 0.f);
  }
  __syncthreads();

  // per-thread state (tid < 64): hl = q_t, b = b_t; global h = 8*rank + hl
  float y_r = 0.f, yhat_r = 0.f, s_old_r = 0.f;
  if (tid < 64) {
    const int h = 8 * (int)rank + q_t;
    float a = ib2[h];
    const float4* wr = reinterpret_cast<const float4*>(iW2 + (size_t)h * Wn);
    const float4* zr = reinterpret_cast<const float4*>(&sm.z2g[b_t * 132]);
    for (int f = 0; f < 32; ++f) a = dot4(wr[f], zr[f], a);
    y_r = a;
    yhat_r = a;
#pragma unroll
    for (int r = 0; r < 8; ++r) st_cluster(yh_rem[r], a);
  }

  vf_eval(sm, tid, z1_rem, z2_rem);  // v0 = vf(ts[0], y0)

  // ---- main scan over 1023 steps ----
#pragma unroll 1
  for (int t = 1; t < Tn; ++t) {
    __syncthreads();  // previous-step dx readers done before overwrite
    // phase A: dx = x[t]-x[t-1]; prefetch x[t+1]; tcur = ts[t]
    if (tid < NBc * Cn) {
      sm.dx[b_p * 36 + c_p] = xn - xp;
      xp = xn;
      if (tid == 0) sm.tcur = xp;  // (b=0,c=0) holds ts[t]
      const int tn = (t + 1 < Tn) ? (t + 1) : t;
      xn = (c_p == 0) ? ts[tn] : ys[((size_t)gb_p * Tn + tn) * Dn + (c_p - 1)];
    }
    __syncthreads();
    // phase B: s_old = v.dx (local h-slice); yhat update; push yhat
    if (tid < 64) {
      const float* vr = &sm.v[b_t * 264 + q_t * Cn];
      const float* dxr = &sm.dx[b_t * 36];
      float s = 0.f;
#pragma unroll
      for (int c = 0; c < Cn; ++c) s = fmaf(vr[c], dxr[c], s);
      const float yh = 2.f * y_r - yhat_r + s;
      yhat_r = yh;
      s_old_r = s;
#pragma unroll
      for (int r = 0; r < 8; ++r) st_cluster(yh_rem[r], yh);
    }

    vf_eval(sm, tid, z1_rem, z2_rem);  // v <- vf(ts[t], yhat)

    // phase F: y += 0.5 * (s_old + v_new.dx)
    if (tid < 64) {
      const float* vr = &sm.v[b_t * 264 + q_t * Cn];
      const float* dxr = &sm.dx[b_t * 36];
      float s = 0.f;
#pragma unroll
      for (int c = 0; c < Cn; ++c) s = fmaf(vr[c], dxr[c], s);
      y_r += 0.5f * (s_old_r + s);
    }
  }

  // ---- readout: gather y slices to rank 0, reduce there ----
  if (tid < 64) st_cluster(yh_rem[0], y_r);  // rank 0's yh[b*68 + 8*rank + hl]
  cluster_sync();
  if (rank == 0 && tid < NBc) {
    float a = rb[0];
    for (int h = 0; h < Hn; ++h) a = fmaf(sm.yh[tid * 68 + h], rW[h], a);
    out[cluster_b0 + tid] = a;
  }
}

}  // namespace

extern "C" void kernel_launch(void* const* d_in, const int* in_sizes, int n_in,
                              void* d_out, int out_size) {
  const float* ts  = (const float*)d_in[0];
  const float* ys  = (const float*)d_in[1];
  const float* iW0 = (const float*)d_in[2];
  const float* ib0 = (const float*)d_in[3];
  const float* iW1 = (const float*)d_in[4];
  const float* ib1 = (const float*)d_in[5];
  const float* iW2 = (const float*)d_in[6];
  const float* ib2 = (const float*)d_in[7];
  const float* vW0 = (const float*)d_in[8];
  const float* vb0 = (const float*)d_in[9];
  const float* vW1 = (const float*)d_in[10];
  const float* vb1 = (const float*)d_in[11];
  const float* vW2 = (const float*)d_in[12];
  const float* vb2 = (const float*)d_in[13];
  const float* rW  = (const float*)d_in[14];
  const float* rb  = (const float*)d_in[15];
  float* out = (float*)d_out;

  cudaFuncSetAttribute(ncde_kernel, cudaFuncAttributeMaxDynamicSharedMemorySize,
                       (int)sizeof(Smem));
  ncde_kernel<<<128, NT, sizeof(Smem)>>>(ts, ys, iW0, ib0, iW1, ib1, iW2, ib2,
                                         vW0, vb0, vW1, vb1, vW2, vb2, rW, rb,
                                         out);
}

// round 8
// speedup vs baseline: 2.1240x; 2.1240x over previous
#include <cuda_runtime.h>
#include <cstdint>

// Neural CDE, B=128, T=1024, D=32, H=64, W=128.
// Streaming design: 64 persistent CTAs x 512 threads, 2 batches/CTA, 1023
// sequential steps with only __syncthreads(). vW2 (2112x128 fp32, 1.08MB)
// streamed from L2 each step. R8 layer-3: quarter-warp-per-row (4 rows per
// LDG.128, minimal 4-line coalescing), packed fma.rn.f32x2 accumulation,
// 3-level shuffle reduction, hand-pipelined distance-2 prefetch. Target:
// the chip LTS floor (64 x 1.08MB / 6300 B/cyc ~= 11K cyc/step).

namespace {

constexpr int Tn = 1024;
constexpr int Dn = 32;
constexpr int Hn = 64;
constexpr int Wn = 128;
constexpr int Cn = Dn + 1;      // 33
constexpr int On = Hn * Cn;     // 2112
constexpr int NB = 2;           // batches per CTA
constexpr int NCTA = 64;
constexpr int NT = 512;         // 16 warps
constexpr int RPW = On / 16;    // 132 rows per warp
constexpr int NBODY = RPW / 4;  // 33 bodies of 4 rows

using u64 = unsigned long long;

struct __align__(16) Smem {
  float vW0[Wn][68];     // padded from 65
  float vW1[Wn][132];    // padded from 128
  float vb0[Wn];
  float vb1[Wn];
  float vb2[On];
  float z1[NB][Wn];
  float z2[NB][Wn];
  float vraw[On][2];     // layer-3 pre-activations (both batches)
  float v[NB][On];       // tanh(vraw + b)
  float y[NB][Hn];       // readout staging
  float inp[NB][68];     // [t, yhat(64), 0-pad]
  float dx[NB][36];
  float rW[Hn];
  float rb;
  float pad_[3];
};

__device__ __forceinline__ float lipswish(float x) {
  float e = __expf(-x);
  return __fdividef(0.909f * x, 1.0f + e);
}
__device__ __forceinline__ float fast_tanh(float x) {
  float p = __expf(2.0f * x);
  return 1.0f - __fdividef(2.0f, p + 1.0f);
}
__device__ __forceinline__ float dot4(float4 a, float4 b, float acc) {
  acc = fmaf(a.x, b.x, acc);
  acc = fmaf(a.y, b.y, acc);
  acc = fmaf(a.z, b.z, acc);
  acc = fmaf(a.w, b.w, acc);
  return acc;
}

// Packed fp32x2 FMA (Blackwell FFMA2): acc.{lo,hi} += a.{lo,hi} * b.{lo,hi}
__device__ __forceinline__ void ffma2(u64& acc, u64 a, u64 b) {
  asm("fma.rn.f32x2 %0, %1, %2, %0;" : "+l"(acc) : "l"(a), "l"(b));
}
__device__ __forceinline__ float hadd2(u64 a) {
  float lo, hi;
  asm("mov.b64 {%0, %1}, %2;" : "=f"(lo), "=f"(hi) : "l"(a));
  return lo + hi;
}

// Load one body (4 rows) worth of weights for this lane: 4x ulonglong2.
// Lane covers floats [kl*4 + j*32, +4) of row (body*4 + sub).
__device__ __forceinline__ void body_load(ulonglong2* w, const float* lane_base,
                                          int body) {
  const float* p = lane_base + (size_t)body * (4 * Wn);
#pragma unroll
  for (int j = 0; j < 4; ++j)
    w[j] = *reinterpret_cast<const ulonglong2*>(p + j * 32);
}

// Compute one body from preloaded weights: 2 packed accums (batch0, batch1),
// 3-level 8-lane reduction, lanes kl==0 hold the row sums.
__device__ __forceinline__ float2 body_compute(const ulonglong2* w,
                                               const ulonglong2* z0,
                                               const ulonglong2* z1) {
  u64 a0 = 0ull, a1 = 0ull;  // (0.0f, 0.0f)
#pragma unroll
  for (int j = 0; j < 4; ++j) {
    ffma2(a0, w[j].x, z0[j].x);
    ffma2(a0, w[j].y, z0[j].y);
    ffma2(a1, w[j].x, z1[j].x);
    ffma2(a1, w[j].y, z1[j].y);
  }
  float s0 = hadd2(a0);
  float s1 = hadd2(a1);
#pragma unroll
  for (int m = 1; m < 8; m <<= 1) {  // reduce across the 8 k-lanes
    s0 += __shfl_xor_sync(0xffffffffu, s0, m);
    s1 += __shfl_xor_sync(0xffffffffu, s1, m);
  }
  return make_float2(s0, s1);
}

// vf(t, y): sm.inp must hold [t, y, 0...]. Writes sm.v. Ends with sync.
__device__ __forceinline__ void vf_eval(Smem& sm, const float* __restrict__ vW2) {
  const int tid = threadIdx.x;

  // ---- layer 1: z1 = lipswish(vW0 @ inp + vb0); 256 threads ----
  if (tid < 256) {
    const int nb = tid >> 7, w = tid & 127;
    float a = sm.vb0[w];
    const float4* wr = reinterpret_cast<const float4*>(&sm.vW0[w][0]);
    const float4* ir = reinterpret_cast<const float4*>(&sm.inp[nb][0]);
#pragma unroll
    for (int q = 0; q < 17; ++q) a = dot4(wr[q], ir[q], a);
    sm.z1[nb][w] = lipswish(a);
  }
  __syncthreads();

  // ---- layer 2: z2 = lipswish(vW1 @ z1 + vb1) ----
  if (tid < 256) {
    const int nb = tid >> 7, w = tid & 127;
    float a = sm.vb1[w];
    const float4* wr = reinterpret_cast<const float4*>(&sm.vW1[w][0]);
    const float4* zr = reinterpret_cast<const float4*>(&sm.z1[nb][0]);
#pragma unroll
    for (int q = 0; q < 32; ++q) a = dot4(wr[q], zr[q], a);
    sm.z2[nb][w] = lipswish(a);
  }
  __syncthreads();

  // ---- layer 3 phase A: vraw = vW2 @ z2 ----
  // Quarter-warp-per-row: sub = lane>>3 picks one of 4 rows per body,
  // kl = lane&7 picks the 16B k-chunk. Each LDG.128 = 4 rows x 128B = 4 lines.
  {
    const int wid = tid >> 5;
    const int lane = tid & 31;
    const int sub = lane >> 3;
    const int kl = lane & 7;

    // hoist this lane's z chunks (k = kl*4 + j*32) for both batches
    ulonglong2 zc0[4], zc1[4];
#pragma unroll
    for (int j = 0; j < 4; ++j) {
      zc0[j] = *reinterpret_cast<const ulonglong2*>(&sm.z2[0][kl * 4 + j * 32]);
      zc1[j] = *reinterpret_cast<const ulonglong2*>(&sm.z2[1][kl * 4 + j * 32]);
    }

    const int rbase = wid * RPW;
    const float* lane_base = vW2 + (size_t)(rbase + sub) * Wn + kl * 4;

    ulonglong2 wA[4], wB[4], wC[4];
    body_load(wA, lane_base, 0);
    body_load(wB, lane_base, 1);

#pragma unroll 1
    for (int i = 0; i < NBODY; i += 3) {  // 33 = 3 * 11, exact
      const int pf2 = (i + 2 < NBODY) ? i + 2 : NBODY - 1;
      const int pf3 = (i + 3 < NBODY) ? i + 3 : NBODY - 1;
      const int pf4 = (i + 4 < NBODY) ? i + 4 : NBODY - 1;

      body_load(wC, lane_base, pf2);
      {
        float2 r = body_compute(wA, zc0, zc1);
        if (kl == 0)
          *reinterpret_cast<float2*>(&sm.vraw[rbase + 4 * i + sub][0]) = r;
      }
      body_load(wA, lane_base, pf3);
      {
        float2 r = body_compute(wB, zc0, zc1);
        if (kl == 0)
          *reinterpret_cast<float2*>(&sm.vraw[rbase + 4 * (i + 1) + sub][0]) = r;
      }
      body_load(wB, lane_base, pf4);
      {
        float2 r = body_compute(wC, zc0, zc1);
        if (kl == 0)
          *reinterpret_cast<float2*>(&sm.vraw[rbase + 4 * (i + 2) + sub][0]) = r;
      }
    }
  }
  __syncthreads();

  // ---- layer 3 phase B: v = tanh(vraw + vb2) ----
  for (int o = tid; o < On; o += NT) {
    const float bias = sm.vb2[o];
    const float2 raw = *reinterpret_cast<const float2*>(&sm.vraw[o][0]);
    sm.v[0][o] = fast_tanh(raw.x + bias);
    sm.v[1][o] = fast_tanh(raw.y + bias);
  }
  __syncthreads();
}

__global__ void __launch_bounds__(NT, 1)
ncde_kernel(const float* __restrict__ ts, const float* __restrict__ ys,
            const float* __restrict__ iW0, const float* __restrict__ ib0,
            const float* __restrict__ iW1, const float* __restrict__ ib1,
            const float* __restrict__ iW2, const float* __restrict__ ib2,
            const float* __restrict__ vW0, const float* __restrict__ vb0,
            const float* __restrict__ vW1, const float* __restrict__ vb1,
            const float* __restrict__ vW2, const float* __restrict__ vb2,
            const float* __restrict__ rW, const float* __restrict__ rb,
            float* __restrict__ out) {
  extern __shared__ char smem_raw[];
  Smem& sm = *reinterpret_cast<Smem*>(smem_raw);
  const int tid = threadIdx.x;
  const int b0 = blockIdx.x * NB;

  // ---- load small weights into SMEM ----
  for (int i = tid; i < Wn * 68; i += NT) {
    int r = i / 68, c = i - r * 68;
    sm.vW0[r][c] = (c < 65) ? vW0[r * 65 + c] : 0.0f;
  }
  for (int i = tid; i < Wn * Wn; i += NT) sm.vW1[i >> 7][i & 127] = vW1[i];
  if (tid < Wn) { sm.vb0[tid] = vb0[tid]; sm.vb1[tid] = vb1[tid]; }
  for (int i = tid; i < On; i += NT) sm.vb2[i] = vb2[i];
  if (tid < Hn) sm.rW[tid] = rW[tid];
  if (tid == 0) sm.rb = rb[0];
  if (tid < NB * 3) sm.inp[tid / 3][65 + (tid % 3)] = 0.0f;  // inp pads

  // ---- x-prefetch registers (tid < 66 only) ----
  const int nb_p = tid / Cn;
  const int c_p = tid - nb_p * Cn;
  const int b_p = b0 + nb_p;
  float xp = 0.0f, xn = 0.0f;
  if (tid < NB * Cn) {
    xp = (c_p == 0) ? ts[0] : ys[((size_t)b_p * Tn) * Dn + (c_p - 1)];
    xn = (c_p == 0) ? ts[1] : ys[((size_t)b_p * Tn + 1) * Dn + (c_p - 1)];
    sm.dx[nb_p][c_p] = xp;                   // stage x0 for initial MLP
    if (c_p == 0) sm.inp[nb_p][0] = xp;      // inp[.][0] = ts[0]
  }
  __syncthreads();

  // ---- initial MLP ----
  if (tid < 256) {
    const int nb = tid >> 7, w = tid & 127;
    float a = ib0[w];
    for (int j = 0; j < Cn; ++j) a = fmaf(iW0[w * Cn + j], sm.dx[nb][j], a);
    sm.z1[nb][w] = fmaxf(a, 0.0f);
  }
  __syncthreads();
  if (tid < 256) {
    const int nb = tid >> 7, w = tid & 127;
    float a = ib1[w];
    for (int j = 0; j < Wn; ++j) a = fmaf(iW1[w * Wn + j], sm.z1[nb][j], a);
    sm.z2[nb][w] = fmaxf(a, 0.0f);
  }
  __syncthreads();

  // per-thread recurrence state (tid < 128): batch nb_s, hidden h_s
  const int nb_s = tid >> 6;
  const int h_s = tid & 63;
  float y_r = 0.0f, yhat_r = 0.0f, s_old_r = 0.0f;
  if (tid < NB * Hn) {
    float a = ib2[h_s];
    for (int j = 0; j < Wn; ++j) a = fmaf(iW2[h_s * Wn + j], sm.z2[nb_s][j], a);
    y_r = a;
    yhat_r = a;
    sm.inp[nb_s][1 + h_s] = a;
  }
  __syncthreads();

  vf_eval(sm, vW2);  // v0 = vf(ts[0], y0)

  // ---- main scan over 1023 steps ----
#pragma unroll 1
  for (int t = 1; t < Tn; ++t) {
    // phase 1: dx = x[t] - x[t-1]; prefetch x[t+1]; publish ts[t]
    if (tid < NB * Cn) {
      sm.dx[nb_p][c_p] = xn - xp;
      xp = xn;
      if (c_p == 0) sm.inp[nb_p][0] = xp;    // = ts[t]
      const int tn = (t + 1 < Tn) ? (t + 1) : t;
      xn = (c_p == 0) ? ts[tn] : ys[((size_t)b_p * Tn + tn) * Dn + (c_p - 1)];
    }
    __syncthreads();

    // phase 2: s_old = v_old . dx ; yhat <- 2y - yhat + s_old
    if (tid < NB * Hn) {
      const float* vr = &sm.v[nb_s][h_s * Cn];
      const float* dxr = &sm.dx[nb_s][0];
      float s = 0.0f;
#pragma unroll
      for (int c = 0; c < Cn; ++c) s = fmaf(vr[c], dxr[c], s);
      const float yh = 2.0f * y_r - yhat_r + s;
      yhat_r = yh;
      s_old_r = s;
      sm.inp[nb_s][1 + h_s] = yh;
    }
    __syncthreads();

    vf_eval(sm, vW2);  // v <- vf(ts[t], yhat)

    // phase 4: y <- y + 0.5 * (s_old + v_new . dx)
    if (tid < NB * Hn) {
      const float* vr = &sm.v[nb_s][h_s * Cn];
      const float* dxr = &sm.dx[nb_s][0];
      float s = 0.0f;
#pragma unroll
      for (int c = 0; c < Cn; ++c) s = fmaf(vr[c], dxr[c], s);
      y_r += 0.5f * (s_old_r + s);
    }
    __syncthreads();
  }

  // ---- readout ----
  if (tid < NB * Hn) sm.y[nb_s][h_s] = y_r;
  __syncthreads();
  if (tid < NB) {
    float a = sm.rb;
    for (int h = 0; h < Hn; ++h) a = fmaf(sm.y[tid][h], sm.rW[h], a);
    out[b0 + tid] = a;
  }
}

}  // namespace

extern "C" void kernel_launch(void* const* d_in, const int* in_sizes, int n_in,
                              void* d_out, int out_size) {
  const float* ts  = (const float*)d_in[0];
  const float* ys  = (const float*)d_in[1];
  const float* iW0 = (const float*)d_in[2];
  const float* ib0 = (const float*)d_in[3];
  const float* iW1 = (const float*)d_in[4];
  const float* ib1 = (const float*)d_in[5];
  const float* iW2 = (const float*)d_in[6];
  const float* ib2 = (const float*)d_in[7];
  const float* vW0 = (const float*)d_in[8];
  const float* vb0 = (const float*)d_in[9];
  const float* vW1 = (const float*)d_in[10];
  const float* vb1 = (const float*)d_in[11];
  const float* vW2 = (const float*)d_in[12];
  const float* vb2 = (const float*)d_in[13];
  const float* rW  = (const float*)d_in[14];
  const float* rb  = (const float*)d_in[15];
  float* out = (float*)d_out;

  cudaFuncSetAttribute(ncde_kernel, cudaFuncAttributeMaxDynamicSharedMemorySize,
                       (int)sizeof(Smem));
  ncde_kernel<<<NCTA, NT, sizeof(Smem)>>>(ts, ys, iW0, ib0, iW1, ib1, iW2, ib2,
                                          vW0, vb0, vW1, vb1, vW2, vb2, rW, rb,
                                          out);
}